// round 12
// baseline (speedup 1.0000x reference)
#include <cuda_runtime.h>
#include <cuda_bf16.h>
#include <cstdint>

#define B_   2
#define DIN  4096
#define LL   4096
#define NN   16
#define RR   128
#define KOUT 160   // R + 2N

// ---------------- scratch (static __device__ per allocation rules) ----------
__device__ float g_dt[B_ * RR * LL];             // dt_low [b][r][l]            (4 MB)
__device__ float g_bc[B_ * LL * 32];             // B/C interleaved [b][l][2n|2n+1]
__device__ float g_delta[(size_t)B_ * DIN * LL]; // softplus'd delta [b][d][l]  (128 MB)

// ---------------- helpers ---------------------------------------------------
__device__ __forceinline__ uint32_t f2tf(float f) {
    uint32_t u;
    asm("cvt.rna.tf32.f32 %0, %1;" : "=r"(u) : "f"(f));
    return u;
}

__device__ __forceinline__ void mma_tf32(float (&d)[4],
                                         uint32_t a0, uint32_t a1, uint32_t a2, uint32_t a3,
                                         uint32_t b0, uint32_t b1) {
    asm("mma.sync.aligned.m16n8k8.row.col.f32.tf32.tf32.f32 "
        "{%0,%1,%2,%3},{%4,%5,%6,%7},{%8,%9},{%0,%1,%2,%3};"
        : "+f"(d[0]), "+f"(d[1]), "+f"(d[2]), "+f"(d[3])
        : "r"(a0), "r"(a1), "r"(a2), "r"(a3), "r"(b0), "r"(b1));
}

__device__ __forceinline__ float softplus_fast(float z) {
    return fmaxf(z, 0.f) + __logf(1.f + __expf(-fabsf(z)));
}

// ---------------------------------------------------------------------------
// GEMM1 v3 (tf32 TC): xd[b,k,l] = sum_d x[b,d,l] * W1[k,d]
// Tile 32(M=k) x 128(N=l), Kc=32, 256 threads (8 warps: 2m x 4n, warp 16x32).
// Register-staged double buffering. grid (32, 5, 2) = 320 CTAs, 2 CTAs/SM.
// blockIdx.y==4 -> B/C rows (k in [128,160)), stored interleaved.
// ---------------------------------------------------------------------------
__global__ __launch_bounds__(256) void gemm1_tc(const float* __restrict__ x,
                                                const float* __restrict__ w1)
{
    const int b  = blockIdx.z;
    const int m0 = blockIdx.y * 32;
    const int l0 = blockIdx.x * 128;
    const float* xb = x + (size_t)b * DIN * LL;

    __shared__ uint32_t As[32][36];     // [k(d)][m] tf32
    __shared__ uint32_t Bs[32][132];    // [k(d)][l] tf32

    const int tid  = threadIdx.x;
    const int warp = tid >> 5;
    const int lane = tid & 31;
    const int wm   = warp >> 2;         // 0..1 -> m offset 16
    const int wn   = warp & 3;          // 0..3 -> n offset 32
    const int g    = lane >> 2;         // 0..7
    const int tg   = lane & 3;          // 0..3

    // staging coords: A one float4/thread, B four float4/thread
    const int ai = tid >> 3;                     // 0..31 (m)
    const int aj = (tid & 7) * 4;                // 0..28 (d)
    const int br[4] = { tid >> 5, (tid + 256) >> 5, (tid + 512) >> 5, (tid + 768) >> 5 };
    const int bc = (tid & 31) * 4;

    float4 sA, sB[4];
    sA = *(const float4*)&w1[(size_t)(m0 + ai) * DIN + aj];
#pragma unroll
    for (int q = 0; q < 4; q++)
        sB[q] = *(const float4*)&xb[(size_t)br[q] * LL + l0 + bc];

    float acc[4][4];
#pragma unroll
    for (int nf = 0; nf < 4; nf++)
#pragma unroll
        for (int r = 0; r < 4; r++) acc[nf][r] = 0.f;

    for (int d0 = 0; d0 < DIN; d0 += 32) {
        As[aj + 0][ai] = f2tf(sA.x);
        As[aj + 1][ai] = f2tf(sA.y);
        As[aj + 2][ai] = f2tf(sA.z);
        As[aj + 3][ai] = f2tf(sA.w);
#pragma unroll
        for (int q = 0; q < 4; q++) {
            uint4 tv = {f2tf(sB[q].x), f2tf(sB[q].y), f2tf(sB[q].z), f2tf(sB[q].w)};
            *(uint4*)&Bs[br[q]][bc] = tv;
        }
        __syncthreads();

        const int dn = d0 + 32;
        if (dn < DIN) {
            sA = *(const float4*)&w1[(size_t)(m0 + ai) * DIN + dn + aj];
#pragma unroll
            for (int q = 0; q < 4; q++)
                sB[q] = *(const float4*)&xb[(size_t)(dn + br[q]) * LL + l0 + bc];
        }

#pragma unroll
        for (int kk = 0; kk < 32; kk += 8) {
            const uint32_t a0 = As[kk + tg    ][wm * 16 + g];
            const uint32_t a1 = As[kk + tg    ][wm * 16 + g + 8];
            const uint32_t a2 = As[kk + tg + 4][wm * 16 + g];
            const uint32_t a3 = As[kk + tg + 4][wm * 16 + g + 8];
#pragma unroll
            for (int nf = 0; nf < 4; nf++) {
                const int nc = wn * 32 + nf * 8 + g;
                const uint32_t b0 = Bs[kk + tg    ][nc];
                const uint32_t b1 = Bs[kk + tg + 4][nc];
                mma_tf32(acc[nf], a0, a1, a2, a3, b0, b1);
            }
        }
        __syncthreads();
    }

    const bool is_bc = (blockIdx.y == 4);   // k in [128,160)
    const int row0 = m0 + wm * 16 + g;
    const int row1 = row0 + 8;
#pragma unroll
    for (int nf = 0; nf < 4; nf++) {
        const int col = l0 + wn * 32 + nf * 8 + 2 * tg;
        if (!is_bc) {
            float2 v0 = {acc[nf][0], acc[nf][1]};
            float2 v1 = {acc[nf][2], acc[nf][3]};
            *(float2*)&g_dt[((size_t)b * RR + row0) * LL + col] = v0;
            *(float2*)&g_dt[((size_t)b * RR + row1) * LL + col] = v1;
        } else {
            // interleaved B/C: n<16 -> B_n at 2n; n>=16 -> C_{n-16} at 2(n-16)+1
            const int n0 = row0 - RR, n1 = row1 - RR;
            const int i0 = ((n0 & 15) << 1) | (n0 >> 4);
            const int i1 = ((n1 & 15) << 1) | (n1 >> 4);
            float* bcb = g_bc + (size_t)b * LL * 32;
            bcb[(size_t)(col    ) * 32 + i0] = acc[nf][0];
            bcb[(size_t)(col + 1) * 32 + i0] = acc[nf][1];
            bcb[(size_t)(col    ) * 32 + i1] = acc[nf][2];
            bcb[(size_t)(col + 1) * 32 + i1] = acc[nf][3];
        }
    }
}

// ---------------------------------------------------------------------------
// GEMM2 (tf32 TC) + softplus: delta[b,d,l] = softplus(sum_r W2[d,r]*dt[b,r,l] + bias[d])
// Block tile 128(M=d) x 128(N=l), K(r)=128 in chunks of 32. 8 warps (4m x 2n).
// Register-staged double buffering across the 4 k-chunks.
// ---------------------------------------------------------------------------
__global__ __launch_bounds__(256) void gemm2_tc(const float* __restrict__ w2,
                                                const float* __restrict__ bias)
{
    const int b  = blockIdx.z;
    const int d0 = blockIdx.y * 128;
    const int l0 = blockIdx.x * 128;

    __shared__ uint32_t As[32][132];    // [k(r)][d] tf32
    __shared__ uint32_t Bs[32][132];    // [k(r)][l] tf32

    const int tid  = threadIdx.x;
    const int warp = tid >> 5;
    const int lane = tid & 31;
    const int wmB  = (warp >> 1) * 32;
    const int wnB  = (warp & 1) * 64;
    const int g    = lane >> 2;
    const int tg   = lane & 3;

    const int Ai[4] = { tid >> 3, (tid+256)>>3, (tid+512)>>3, (tid+768)>>3 };  // d 0..127
    const int Aj    = (tid & 7) * 4;                                           // r 0..28
    const int Br[4] = { tid >> 5, (tid+256)>>5, (tid+512)>>5, (tid+768)>>5 };  // r 0..31
    const int Bc    = (tid & 31) * 4;                                          // l 0..124

    float4 sA[4], sB[4];
#pragma unroll
    for (int q = 0; q < 4; q++) {
        sA[q] = *(const float4*)&w2[(size_t)(d0 + Ai[q]) * RR + Aj];
        sB[q] = *(const float4*)&g_dt[((size_t)b * RR + Br[q]) * LL + l0 + Bc];
    }

    float acc[2][8][4];
#pragma unroll
    for (int mf = 0; mf < 2; mf++)
#pragma unroll
        for (int nf = 0; nf < 8; nf++)
#pragma unroll
            for (int r = 0; r < 4; r++) acc[mf][nf][r] = 0.f;

    for (int r0 = 0; r0 < RR; r0 += 32) {
#pragma unroll
        for (int q = 0; q < 4; q++) {
            As[Aj + 0][Ai[q]] = f2tf(sA[q].x);
            As[Aj + 1][Ai[q]] = f2tf(sA[q].y);
            As[Aj + 2][Ai[q]] = f2tf(sA[q].z);
            As[Aj + 3][Ai[q]] = f2tf(sA[q].w);
            uint4 tv = {f2tf(sB[q].x), f2tf(sB[q].y), f2tf(sB[q].z), f2tf(sB[q].w)};
            *(uint4*)&Bs[Br[q]][Bc] = tv;
        }
        __syncthreads();

        const int rn = r0 + 32;
        if (rn < RR) {
#pragma unroll
            for (int q = 0; q < 4; q++) {
                sA[q] = *(const float4*)&w2[(size_t)(d0 + Ai[q]) * RR + rn + Aj];
                sB[q] = *(const float4*)&g_dt[((size_t)b * RR + rn + Br[q]) * LL + l0 + Bc];
            }
        }

#pragma unroll
        for (int kk = 0; kk < 32; kk += 8) {
            uint32_t a[2][4];
#pragma unroll
            for (int mf = 0; mf < 2; mf++) {
                a[mf][0] = As[kk + tg    ][wmB + mf * 16 + g];
                a[mf][1] = As[kk + tg    ][wmB + mf * 16 + g + 8];
                a[mf][2] = As[kk + tg + 4][wmB + mf * 16 + g];
                a[mf][3] = As[kk + tg + 4][wmB + mf * 16 + g + 8];
            }
#pragma unroll
            for (int nf = 0; nf < 8; nf++) {
                const int nc = wnB + nf * 8 + g;
                const uint32_t b0 = Bs[kk + tg    ][nc];
                const uint32_t b1 = Bs[kk + tg + 4][nc];
#pragma unroll
                for (int mf = 0; mf < 2; mf++)
                    mma_tf32(acc[mf][nf], a[mf][0], a[mf][1], a[mf][2], a[mf][3], b0, b1);
            }
        }
        __syncthreads();
    }

#pragma unroll
    for (int mf = 0; mf < 2; mf++) {
        const int row0 = d0 + wmB + mf * 16 + g;
        const int row1 = row0 + 8;
        const float bi0 = bias[row0];
        const float bi1 = bias[row1];
#pragma unroll
        for (int nf = 0; nf < 8; nf++) {
            const int col = l0 + wnB + nf * 8 + 2 * tg;
            float2 v0 = {softplus_fast(acc[mf][nf][0] + bi0),
                         softplus_fast(acc[mf][nf][1] + bi0)};
            float2 v1 = {softplus_fast(acc[mf][nf][2] + bi1),
                         softplus_fast(acc[mf][nf][3] + bi1)};
            *(float2*)&g_delta[((size_t)b * DIN + row0) * LL + col] = v0;
            *(float2*)&g_delta[((size_t)b * DIN + row1) * LL + col] = v1;
        }
    }
}

// ---------------------------------------------------------------------------
// Scan v3: 256 threads = 16 groups (16 consecutive d, same b). Lane n owns h[n].
// Chunks of 32 timesteps staged in smem (bc interleaved + delta + x).
// Inner loop: one LDS.64 for (B,C), exp/fma, 4-shfl reduce-scatter.
// ---------------------------------------------------------------------------
#define CH 32
__global__ __launch_bounds__(256) void scan_kernel(const float* __restrict__ x,
                                                   const float* __restrict__ A_log,
                                                   const float* __restrict__ Dvec,
                                                   float* __restrict__ y)
{
    __shared__ float del_s[16][CH];
    __shared__ float x_s[16][CH];
    __shared__ float bc_s[CH * 32];

    const int tid = threadIdx.x;
    const int lg  = tid >> 4;            // local group 0..15
    const int n   = tid & 15;
    const int gb  = blockIdx.x * 16;     // global group base
    const int b   = gb >> 12;
    const int d   = (gb & 4095) + lg;

    const size_t base = ((size_t)b * DIN + d) * LL;
    const float  a    = -__expf(A_log[d * NN + n]);
    const float  dD   = (n == 0) ? Dvec[d] : 0.f;
    const float* bcb  = g_bc + (size_t)b * LL * 32;
    const int jm = ((n & 1) << 1) | ((n >> 1) & 1);

    // staging roles: all threads load bc; tid<128 -> delta rows, else -> x rows
    const int sg = (tid & 127) >> 3;           // staged group 0..15
    const int sq = (tid & 7) * 4;              // offset within chunk
    const size_t srow = ((size_t)b * DIN + (gb & 4095) + sg) * LL;
    const float* sptr = (tid < 128 ? (const float*)g_delta : x) + srow;

    float4 rbc = *(const float4*)&bcb[(size_t)0 * 32 + tid * 4];
    float4 rdu = *(const float4*)&sptr[sq];

    float h = 0.f;
    for (int l0 = 0; l0 < LL; l0 += CH) {
        *(float4*)&bc_s[tid * 4] = rbc;
        if (tid < 128) *(float4*)&del_s[sg][sq] = rdu;
        else           *(float4*)&x_s[sg][sq]   = rdu;
        __syncthreads();

        const int ln = l0 + CH;
        if (ln < LL) {
            rbc = *(const float4*)&bcb[(size_t)ln * 32 + tid * 4];
            rdu = *(const float4*)&sptr[ln + sq];
        }

#pragma unroll
        for (int jj = 0; jj < CH; jj += 4) {
            const float4 tz = *(const float4*)&del_s[lg][jj];
            const float4 uu = *(const float4*)&x_s[lg][jj];
            const float tj[4] = {tz.x, tz.y, tz.z, tz.w};
            const float uj[4] = {uu.x, uu.y, uu.z, uu.w};
            float p[4];
#pragma unroll
            for (int j = 0; j < 4; j++) {
                const float t  = tj[j];
                const float u  = uj[j];
                const float2 bcv = *(const float2*)&bc_s[(jj + j) * 32 + 2 * n];
                const float dA = __expf(t * a);
                h = fmaf(h, dA, (t * u) * bcv.x);
                p[j] = fmaf(u, dD, h * bcv.y);
            }
            // reduce-scatter over 16 lanes: 4 shfls for 4 values
            const bool o1 = (n & 1);
            float s0 = o1 ? p[0] : p[2];
            float s1 = o1 ? p[1] : p[3];
            float r0 = __shfl_xor_sync(0xffffffffu, s0, 1);
            float r1 = __shfl_xor_sync(0xffffffffu, s1, 1);
            float u0 = (o1 ? p[2] : p[0]) + r0;
            float u1 = (o1 ? p[3] : p[1]) + r1;
            const bool o2 = (n & 2);
            float s2 = o2 ? u0 : u1;
            float r2 = __shfl_xor_sync(0xffffffffu, s2, 2);
            float v  = (o2 ? u1 : u0) + r2;
            v += __shfl_xor_sync(0xffffffffu, v, 4);
            v += __shfl_xor_sync(0xffffffffu, v, 8);
            if (n < 4) y[base + l0 + jj + jm] = v;
        }
        __syncthreads();
    }
}

// ---------------------------------------------------------------------------
extern "C" void kernel_launch(void* const* d_in, const int* in_sizes, int n_in,
                              void* d_out, int out_size)
{
    const float* x     = (const float*)d_in[0];  // (B, D, L)
    const float* A_log = (const float*)d_in[1];  // (D, N)
    const float* Dvec  = (const float*)d_in[2];  // (D,)
    const float* xpw   = (const float*)d_in[3];  // (160, D)
    const float* dtw   = (const float*)d_in[4];  // (D, R)
    const float* dtb   = (const float*)d_in[5];  // (D,)
    float* y = (float*)d_out;

    {
        dim3 grid(LL / 128, KOUT / 32, B_);   // 32 x 5 x 2 = 320
        gemm1_tc<<<grid, 256>>>(x, xpw);
    }
    {
        dim3 grid(LL / 128, DIN / 128, B_);   // 32 x 32 x 2 = 2048
        gemm2_tc<<<grid, 256>>>(dtw, dtb);
    }
    {
        const int blocks = (B_ * DIN) / 16;   // 512 blocks of 16 groups
        scan_kernel<<<blocks, 256>>>(x, A_log, Dvec, y);
    }
}

// round 13
// speedup vs baseline: 1.1930x; 1.1930x over previous
#include <cuda_runtime.h>
#include <cuda_bf16.h>
#include <cstdint>

#define B_   2
#define DIN  4096
#define LL   4096
#define NN   16
#define RR   128
#define KOUT 160   // R + 2N
#define DHALF (DIN / 2)

// ---------------- scratch (static __device__ per allocation rules) ----------
// split-k partial buffers; consumers sum them.
__device__ float g_dt0[B_ * RR * LL];
__device__ float g_dt1[B_ * RR * LL];
__device__ float g_bc0[B_ * LL * 32];   // quad layout [b][l][4n..] = B_n,C_n,B_{n+8},C_{n+8}
__device__ float g_bc1[B_ * LL * 32];
__device__ float g_delta[(size_t)B_ * DIN * LL]; // softplus'd delta [b][d][l]

// ---------------- helpers ---------------------------------------------------
__device__ __forceinline__ uint32_t f2tf(float f) {
    uint32_t u;
    asm("cvt.rna.tf32.f32 %0, %1;" : "=r"(u) : "f"(f));
    return u;
}

__device__ __forceinline__ void mma_tf32(float (&d)[4],
                                         uint32_t a0, uint32_t a1, uint32_t a2, uint32_t a3,
                                         uint32_t b0, uint32_t b1) {
    asm("mma.sync.aligned.m16n8k8.row.col.f32.tf32.tf32.f32 "
        "{%0,%1,%2,%3},{%4,%5,%6,%7},{%8,%9},{%0,%1,%2,%3};"
        : "+f"(d[0]), "+f"(d[1]), "+f"(d[2]), "+f"(d[3])
        : "r"(a0), "r"(a1), "r"(a2), "r"(a3), "r"(b0), "r"(b1));
}

__device__ __forceinline__ float softplus_fast(float z) {
    return fmaxf(z, 0.f) + __logf(1.f + __expf(-fabsf(z)));
}

// quad index for B/C row t (t = k-128, 0..31): B_s (t<16) / C_{t-16}
__device__ __forceinline__ int qidx(int t) {
    return ((t & 7) << 2) | (((t >> 3) & 1) << 1) | (t >> 4);
}

// ---------------------------------------------------------------------------
// GEMM1 v4 (tf32 TC, split-k=2): xd[b,k,l] = sum_d x[b,d,l] * W1[k,d]
// Tile 32(M=k) x 128(N=l), Kc=32, 128 threads (4 warps: 2m x 2n, warp 16x64).
// Register-staged double buffering. grid (32, 5, B_*2) = 640 CTAs.
// blockIdx.z&1 selects k-half and output partial buffer.
// ---------------------------------------------------------------------------
__global__ __launch_bounds__(128) void gemm1_tc(const float* __restrict__ x,
                                                const float* __restrict__ w1)
{
    const int bz = blockIdx.z;
    const int b  = bz >> 1;
    const int kh = bz & 1;
    const int m0 = blockIdx.y * 32;
    const int l0 = blockIdx.x * 128;
    const int dbeg = kh * DHALF;
    const int dend = dbeg + DHALF;
    const float* xb = x + (size_t)b * DIN * LL;

    __shared__ uint32_t As[32][36];     // [k(d)][m] tf32
    __shared__ uint32_t Bs[32][132];    // [k(d)][l] tf32

    const int tid  = threadIdx.x;
    const int warp = tid >> 5;
    const int lane = tid & 31;
    const int wm   = warp >> 1;         // 0..1 -> m offset 16
    const int wn   = warp & 1;          // 0..1 -> n offset 64
    const int g    = lane >> 2;         // 0..7
    const int tg   = lane & 3;          // 0..3

    const int ai[2] = { tid >> 3, (tid + 128) >> 3 };              // m row 0..31
    const int aj    = (tid & 7) * 4;                               // k col 0..28
    const int br[8] = { tid >> 5, (tid+128)>>5, (tid+256)>>5, (tid+384)>>5,
                        (tid+512)>>5, (tid+640)>>5, (tid+768)>>5, (tid+896)>>5 };
    const int bc    = (tid & 31) * 4;

    float4 sA[2], sB[8];
#pragma unroll
    for (int q = 0; q < 2; q++)
        sA[q] = *(const float4*)&w1[(size_t)(m0 + ai[q]) * DIN + dbeg + aj];
#pragma unroll
    for (int q = 0; q < 8; q++)
        sB[q] = *(const float4*)&xb[(size_t)(dbeg + br[q]) * LL + l0 + bc];

    float acc[8][4];
#pragma unroll
    for (int nf = 0; nf < 8; nf++)
#pragma unroll
        for (int r = 0; r < 4; r++) acc[nf][r] = 0.f;

    for (int d0 = dbeg; d0 < dend; d0 += 32) {
#pragma unroll
        for (int q = 0; q < 2; q++) {
            As[aj + 0][ai[q]] = f2tf(sA[q].x);
            As[aj + 1][ai[q]] = f2tf(sA[q].y);
            As[aj + 2][ai[q]] = f2tf(sA[q].z);
            As[aj + 3][ai[q]] = f2tf(sA[q].w);
        }
#pragma unroll
        for (int q = 0; q < 8; q++) {
            uint4 tv = {f2tf(sB[q].x), f2tf(sB[q].y), f2tf(sB[q].z), f2tf(sB[q].w)};
            *(uint4*)&Bs[br[q]][bc] = tv;
        }
        __syncthreads();

        const int dn = d0 + 32;
        if (dn < dend) {
#pragma unroll
            for (int q = 0; q < 2; q++)
                sA[q] = *(const float4*)&w1[(size_t)(m0 + ai[q]) * DIN + dn + aj];
#pragma unroll
            for (int q = 0; q < 8; q++)
                sB[q] = *(const float4*)&xb[(size_t)(dn + br[q]) * LL + l0 + bc];
        }

#pragma unroll
        for (int kk = 0; kk < 32; kk += 8) {
            const uint32_t a0 = As[kk + tg    ][wm * 16 + g];
            const uint32_t a1 = As[kk + tg    ][wm * 16 + g + 8];
            const uint32_t a2 = As[kk + tg + 4][wm * 16 + g];
            const uint32_t a3 = As[kk + tg + 4][wm * 16 + g + 8];
#pragma unroll
            for (int nf = 0; nf < 8; nf++) {
                const int nc = wn * 64 + nf * 8 + g;
                const uint32_t b0 = Bs[kk + tg    ][nc];
                const uint32_t b1 = Bs[kk + tg + 4][nc];
                mma_tf32(acc[nf], a0, a1, a2, a3, b0, b1);
            }
        }
        __syncthreads();
    }

    float* dtO = (kh ? g_dt1 : g_dt0);
    float* bcO = (kh ? g_bc1 : g_bc0) + (size_t)b * LL * 32;
    const bool is_bc = (blockIdx.y == 4);   // k in [128,160)
    const int row0 = m0 + wm * 16 + g;
    const int row1 = row0 + 8;
#pragma unroll
    for (int nf = 0; nf < 8; nf++) {
        const int col = l0 + wn * 64 + nf * 8 + 2 * tg;
        if (!is_bc) {
            float2 v0 = {acc[nf][0], acc[nf][1]};
            float2 v1 = {acc[nf][2], acc[nf][3]};
            *(float2*)&dtO[((size_t)b * RR + row0) * LL + col] = v0;
            *(float2*)&dtO[((size_t)b * RR + row1) * LL + col] = v1;
        } else {
            const int i0 = qidx(row0 - RR);
            const int i1 = qidx(row1 - RR);
            bcO[(size_t)(col    ) * 32 + i0] = acc[nf][0];
            bcO[(size_t)(col + 1) * 32 + i0] = acc[nf][1];
            bcO[(size_t)(col    ) * 32 + i1] = acc[nf][2];
            bcO[(size_t)(col + 1) * 32 + i1] = acc[nf][3];
        }
    }
}

// ---------------------------------------------------------------------------
// GEMM2 (tf32 TC) + softplus: delta[b,d,l] = softplus(sum_r W2[d,r]*dt[b,r,l] + bias[d])
// Block tile 128(M=d) x 128(N=l), K(r)=128 in chunks of 32. 8 warps (4m x 2n).
// dt = g_dt0 + g_dt1 (split-k partials summed at staging).
// ---------------------------------------------------------------------------
__global__ __launch_bounds__(256) void gemm2_tc(const float* __restrict__ w2,
                                                const float* __restrict__ bias)
{
    const int b  = blockIdx.z;
    const int d0 = blockIdx.y * 128;
    const int l0 = blockIdx.x * 128;

    __shared__ uint32_t As[32][132];    // [k(r)][d] tf32
    __shared__ uint32_t Bs[32][132];    // [k(r)][l] tf32

    const int tid  = threadIdx.x;
    const int warp = tid >> 5;
    const int lane = tid & 31;
    const int wmB  = (warp >> 1) * 32;
    const int wnB  = (warp & 1) * 64;
    const int g    = lane >> 2;
    const int tg   = lane & 3;

    const int Ai[4] = { tid >> 3, (tid+256)>>3, (tid+512)>>3, (tid+768)>>3 };  // d 0..127
    const int Aj    = (tid & 7) * 4;                                           // r 0..28
    const int Br[4] = { tid >> 5, (tid+256)>>5, (tid+512)>>5, (tid+768)>>5 };  // r 0..31
    const int Bc    = (tid & 31) * 4;                                          // l 0..124

    float4 sA[4], sB[4], sBb[4];
#pragma unroll
    for (int q = 0; q < 4; q++) {
        const size_t off = ((size_t)b * RR + Br[q]) * LL + l0 + Bc;
        sA[q]  = *(const float4*)&w2[(size_t)(d0 + Ai[q]) * RR + Aj];
        sB[q]  = *(const float4*)&g_dt0[off];
        sBb[q] = *(const float4*)&g_dt1[off];
    }

    float acc[2][8][4];
#pragma unroll
    for (int mf = 0; mf < 2; mf++)
#pragma unroll
        for (int nf = 0; nf < 8; nf++)
#pragma unroll
            for (int r = 0; r < 4; r++) acc[mf][nf][r] = 0.f;

    for (int r0 = 0; r0 < RR; r0 += 32) {
#pragma unroll
        for (int q = 0; q < 4; q++) {
            As[Aj + 0][Ai[q]] = f2tf(sA[q].x);
            As[Aj + 1][Ai[q]] = f2tf(sA[q].y);
            As[Aj + 2][Ai[q]] = f2tf(sA[q].z);
            As[Aj + 3][Ai[q]] = f2tf(sA[q].w);
            uint4 tv = {f2tf(sB[q].x + sBb[q].x), f2tf(sB[q].y + sBb[q].y),
                        f2tf(sB[q].z + sBb[q].z), f2tf(sB[q].w + sBb[q].w)};
            *(uint4*)&Bs[Br[q]][Bc] = tv;
        }
        __syncthreads();

        const int rn = r0 + 32;
        if (rn < RR) {
#pragma unroll
            for (int q = 0; q < 4; q++) {
                const size_t off = ((size_t)b * RR + rn + Br[q]) * LL + l0 + Bc;
                sA[q]  = *(const float4*)&w2[(size_t)(d0 + Ai[q]) * RR + rn + Aj];
                sB[q]  = *(const float4*)&g_dt0[off];
                sBb[q] = *(const float4*)&g_dt1[off];
            }
        }

#pragma unroll
        for (int kk = 0; kk < 32; kk += 8) {
            uint32_t a[2][4];
#pragma unroll
            for (int mf = 0; mf < 2; mf++) {
                a[mf][0] = As[kk + tg    ][wmB + mf * 16 + g];
                a[mf][1] = As[kk + tg    ][wmB + mf * 16 + g + 8];
                a[mf][2] = As[kk + tg + 4][wmB + mf * 16 + g];
                a[mf][3] = As[kk + tg + 4][wmB + mf * 16 + g + 8];
            }
#pragma unroll
            for (int nf = 0; nf < 8; nf++) {
                const int nc = wnB + nf * 8 + g;
                const uint32_t b0 = Bs[kk + tg    ][nc];
                const uint32_t b1 = Bs[kk + tg + 4][nc];
#pragma unroll
                for (int mf = 0; mf < 2; mf++)
                    mma_tf32(acc[mf][nf], a[mf][0], a[mf][1], a[mf][2], a[mf][3], b0, b1);
            }
        }
        __syncthreads();
    }

#pragma unroll
    for (int mf = 0; mf < 2; mf++) {
        const int row0 = d0 + wmB + mf * 16 + g;
        const int row1 = row0 + 8;
        const float bi0 = bias[row0];
        const float bi1 = bias[row1];
#pragma unroll
        for (int nf = 0; nf < 8; nf++) {
            const int col = l0 + wnB + nf * 8 + 2 * tg;
            float2 v0 = {softplus_fast(acc[mf][nf][0] + bi0),
                         softplus_fast(acc[mf][nf][1] + bi0)};
            float2 v1 = {softplus_fast(acc[mf][nf][2] + bi1),
                         softplus_fast(acc[mf][nf][3] + bi1)};
            *(float2*)&g_delta[((size_t)b * DIN + row0) * LL + col] = v0;
            *(float2*)&g_delta[((size_t)b * DIN + row1) * LL + col] = v1;
        }
    }
}

// ---------------------------------------------------------------------------
// Scan v4: 128 threads = 16 groups of 8 lanes; lane n owns states n and n+8.
// B/C quads [B_n, C_n, B_{n+8}, C_{n+8}] -> one LDS.128 per step per lane.
// Chunks of 32 timesteps staged in smem; bc = sum of split-k partials.
// Reduction: 3-stage reduce-scatter over 8 lanes (4 shfl per 4 steps).
// ---------------------------------------------------------------------------
#define CH 32
__global__ __launch_bounds__(128) void scan_kernel(const float* __restrict__ x,
                                                   const float* __restrict__ A_log,
                                                   const float* __restrict__ Dvec,
                                                   float* __restrict__ y)
{
    __shared__ float del_s[16][CH];
    __shared__ float x_s[16][CH];
    __shared__ float bc_s[CH * 32];

    const int tid = threadIdx.x;
    const int lg  = tid >> 3;            // local group 0..15
    const int n   = tid & 7;             // lane within group
    const int gb  = blockIdx.x * 16;     // (b,d)-group base
    const int b   = gb >> 12;
    const int dbase = gb & 4095;
    const int d   = dbase + lg;

    const size_t base = ((size_t)b * DIN + d) * LL;
    const float  a0   = -__expf(A_log[d * NN + n]);
    const float  a1   = -__expf(A_log[d * NN + n + 8]);
    const float  dD   = (n == 0) ? Dvec[d] : 0.f;
    const int jm = ((n & 1) << 1) | ((n >> 1) & 1);

    const float* bc0 = g_bc0 + (size_t)b * LL * 32;
    const float* bc1 = g_bc1 + (size_t)b * LL * 32;

    // staging coords
    const int srow = tid >> 3;                 // 0..15 (delta/x row)
    const int scol = (tid & 7) * 4;            // 0..28 (chunk offset)
    const size_t rowoff = ((size_t)b * DIN + dbase + srow) * LL;
    // bc: 2 float4 per thread: idx = tid + q*128 -> col=idx>>3, off=(idx&7)*4
    const int bcol[2] = { tid >> 3, (tid + 128) >> 3 };
    const int boff[2] = { (tid & 7) * 4, (tid & 7) * 4 };

    float4 rbc[2], rdel, rx;
#pragma unroll
    for (int q = 0; q < 2; q++) {
        const size_t o = (size_t)bcol[q] * 32 + boff[q];
        float4 v0 = *(const float4*)&bc0[o];
        float4 v1 = *(const float4*)&bc1[o];
        rbc[q] = make_float4(v0.x + v1.x, v0.y + v1.y, v0.z + v1.z, v0.w + v1.w);
    }
    rdel = *(const float4*)&g_delta[rowoff + scol];
    rx   = *(const float4*)&x[rowoff + scol];

    float h0 = 0.f, h1 = 0.f;
    for (int l0 = 0; l0 < LL; l0 += CH) {
        // commit staged chunk
#pragma unroll
        for (int q = 0; q < 2; q++)
            *(float4*)&bc_s[bcol[q] * 32 + boff[q]] = rbc[q];
        *(float4*)&del_s[srow][scol] = rdel;
        *(float4*)&x_s[srow][scol]   = rx;
        __syncthreads();

        // prefetch next chunk
        const int ln = l0 + CH;
        if (ln < LL) {
#pragma unroll
            for (int q = 0; q < 2; q++) {
                const size_t o = (size_t)(ln + bcol[q]) * 32 + boff[q];
                float4 v0 = *(const float4*)&bc0[o];
                float4 v1 = *(const float4*)&bc1[o];
                rbc[q] = make_float4(v0.x + v1.x, v0.y + v1.y, v0.z + v1.z, v0.w + v1.w);
            }
            rdel = *(const float4*)&g_delta[rowoff + ln + scol];
            rx   = *(const float4*)&x[rowoff + ln + scol];
        }

#pragma unroll
        for (int jj = 0; jj < CH; jj += 4) {
            const float4 tz = *(const float4*)&del_s[lg][jj];
            const float4 uu = *(const float4*)&x_s[lg][jj];
            const float tj[4] = {tz.x, tz.y, tz.z, tz.w};
            const float uj[4] = {uu.x, uu.y, uu.z, uu.w};
            float p[4];
#pragma unroll
            for (int j = 0; j < 4; j++) {
                const float t = tj[j];
                const float u = uj[j];
                const float4 q = *(const float4*)&bc_s[(jj + j) * 32 + n * 4];
                const float e0 = __expf(t * a0);
                const float e1 = __expf(t * a1);
                const float tu = t * u;
                h0 = fmaf(h0, e0, tu * q.x);
                h1 = fmaf(h1, e1, tu * q.z);
                p[j] = fmaf(h0, q.y, fmaf(h1, q.w, u * dD));
            }
            // reduce-scatter over 8 lanes: 4 shfls for 4 values
            const bool o1 = (n & 1);
            float s0 = o1 ? p[0] : p[2];
            float s1 = o1 ? p[1] : p[3];
            float r0 = __shfl_xor_sync(0xffffffffu, s0, 1);
            float r1 = __shfl_xor_sync(0xffffffffu, s1, 1);
            float u0 = (o1 ? p[2] : p[0]) + r0;
            float u1 = (o1 ? p[3] : p[1]) + r1;
            const bool o2 = (n & 2);
            float s2 = o2 ? u0 : u1;
            float r2 = __shfl_xor_sync(0xffffffffu, s2, 2);
            float v  = (o2 ? u1 : u0) + r2;
            v += __shfl_xor_sync(0xffffffffu, v, 4);
            if (n < 4) y[base + l0 + jj + jm] = v;
        }
        __syncthreads();
    }
}

// ---------------------------------------------------------------------------
extern "C" void kernel_launch(void* const* d_in, const int* in_sizes, int n_in,
                              void* d_out, int out_size)
{
    const float* x     = (const float*)d_in[0];  // (B, D, L)
    const float* A_log = (const float*)d_in[1];  // (D, N)
    const float* Dvec  = (const float*)d_in[2];  // (D,)
    const float* xpw   = (const float*)d_in[3];  // (160, D)
    const float* dtw   = (const float*)d_in[4];  // (D, R)
    const float* dtb   = (const float*)d_in[5];  // (D,)
    float* y = (float*)d_out;

    {
        dim3 grid(LL / 128, KOUT / 32, B_ * 2);   // 32 x 5 x 4 = 640 (split-k)
        gemm1_tc<<<grid, 128>>>(x, xpw);
    }
    {
        dim3 grid(LL / 128, DIN / 128, B_);       // 32 x 32 x 2 = 2048
        gemm2_tc<<<grid, 256>>>(dtw, dtb);
    }
    {
        const int blocks = (B_ * DIN) / 16;       // 512 blocks of 16 groups
        scan_kernel<<<blocks, 128>>>(x, A_log, Dvec, y);
    }
}

// round 15
// speedup vs baseline: 1.2830x; 1.0754x over previous
#include <cuda_runtime.h>
#include <cuda_bf16.h>
#include <cstdint>

#define B_   2
#define DIN  4096
#define LL   4096
#define NN   16
#define RR   128
#define KOUT 160   // R + 2N
#define DHALF (DIN / 2)

// ---------------- scratch (static __device__ per allocation rules) ----------
__device__ float g_dt0[B_ * RR * LL];
__device__ float g_dt1[B_ * RR * LL];
__device__ float g_bc0[B_ * LL * 32];   // quad layout [b][l][4n..] = B_n,C_n,B_{n+8},C_{n+8}
__device__ float g_bc1[B_ * LL * 32];
__device__ float g_delta[(size_t)B_ * DIN * LL]; // softplus'd delta [b][d][l]

// ---------------- helpers ---------------------------------------------------
__device__ __forceinline__ uint32_t f2tf(float f) {
    uint32_t u;
    asm("cvt.rna.tf32.f32 %0, %1;" : "=r"(u) : "f"(f));
    return u;
}

__device__ __forceinline__ void mma_tf32(float (&d)[4],
                                         uint32_t a0, uint32_t a1, uint32_t a2, uint32_t a3,
                                         uint32_t b0, uint32_t b1) {
    asm("mma.sync.aligned.m16n8k8.row.col.f32.tf32.tf32.f32 "
        "{%0,%1,%2,%3},{%4,%5,%6,%7},{%8,%9},{%0,%1,%2,%3};"
        : "+f"(d[0]), "+f"(d[1]), "+f"(d[2]), "+f"(d[3])
        : "r"(a0), "r"(a1), "r"(a2), "r"(a3), "r"(b0), "r"(b1));
}

__device__ __forceinline__ float softplus_fast(float z) {
    return fmaxf(z, 0.f) + __logf(1.f + __expf(-fabsf(z)));
}

// quad index for B/C row t (t = k-128, 0..31): B_s (t<16) / C_{t-16}
__device__ __forceinline__ int qidx(int t) {
    return ((t & 7) << 2) | (((t >> 3) & 1) << 1) | (t >> 4);
}

// ---------------------------------------------------------------------------
// GEMM1 v5 (tf32 TC, split-k=2, 64-row tiles): xd[b,k,l] = sum_d x[b,d,l]*W1[k,d]
// grid (32, 3, B_*2). y in {0,1}: 64-row dt tile (warp tile 32x64, 1.5 LDS/MMA).
// y==2: 32-row B/C tile (warp tile 16x64). 128 threads, reg double buffering.
// ---------------------------------------------------------------------------
__global__ __launch_bounds__(128) void gemm1_tc(const float* __restrict__ x,
                                                const float* __restrict__ w1)
{
    const int bz = blockIdx.z;
    const int b  = bz >> 1;
    const int kh = bz & 1;
    const bool is64 = (blockIdx.y < 2);
    const int m0 = blockIdx.y * 64;         // y==2 -> 128
    const int l0 = blockIdx.x * 128;
    const int dbeg = kh * DHALF;
    const int dend = dbeg + DHALF;
    const float* xb = x + (size_t)b * DIN * LL;

    __shared__ uint32_t As[32][68];     // [k(d)][m] tf32, m up to 64
    __shared__ uint32_t Bs[32][132];    // [k(d)][l] tf32

    const int tid  = threadIdx.x;
    const int warp = tid >> 5;
    const int lane = tid & 31;
    const int wm   = warp >> 1;         // 0..1
    const int wn   = warp & 1;          // 0..1 -> n offset 64
    const int g    = lane >> 2;         // 0..7
    const int tg   = lane & 3;          // 0..3

    const int ai[4] = { tid >> 3, (tid+128) >> 3, (tid+256) >> 3, (tid+384) >> 3 }; // m 0..63
    const int aj    = (tid & 7) * 4;                                                 // d 0..28
    const int nAq   = is64 ? 4 : 2;
    const int br[8] = { tid >> 5, (tid+128)>>5, (tid+256)>>5, (tid+384)>>5,
                        (tid+512)>>5, (tid+640)>>5, (tid+768)>>5, (tid+896)>>5 };
    const int bc    = (tid & 31) * 4;

    float4 sA[4], sB[8];
#pragma unroll
    for (int q = 0; q < 4; q++)
        if (q < nAq)
            sA[q] = *(const float4*)&w1[(size_t)(m0 + ai[q]) * DIN + dbeg + aj];
#pragma unroll
    for (int q = 0; q < 8; q++)
        sB[q] = *(const float4*)&xb[(size_t)(dbeg + br[q]) * LL + l0 + bc];

    float acc[2][8][4];
#pragma unroll
    for (int mf = 0; mf < 2; mf++)
#pragma unroll
        for (int nf = 0; nf < 8; nf++)
#pragma unroll
            for (int r = 0; r < 4; r++) acc[mf][nf][r] = 0.f;

    for (int d0 = dbeg; d0 < dend; d0 += 32) {
#pragma unroll
        for (int q = 0; q < 4; q++)
            if (q < nAq) {
                As[aj + 0][ai[q]] = f2tf(sA[q].x);
                As[aj + 1][ai[q]] = f2tf(sA[q].y);
                As[aj + 2][ai[q]] = f2tf(sA[q].z);
                As[aj + 3][ai[q]] = f2tf(sA[q].w);
            }
#pragma unroll
        for (int q = 0; q < 8; q++) {
            uint4 tv = {f2tf(sB[q].x), f2tf(sB[q].y), f2tf(sB[q].z), f2tf(sB[q].w)};
            *(uint4*)&Bs[br[q]][bc] = tv;
        }
        __syncthreads();

        const int dn = d0 + 32;
        if (dn < dend) {
#pragma unroll
            for (int q = 0; q < 4; q++)
                if (q < nAq)
                    sA[q] = *(const float4*)&w1[(size_t)(m0 + ai[q]) * DIN + dn + aj];
#pragma unroll
            for (int q = 0; q < 8; q++)
                sB[q] = *(const float4*)&xb[(size_t)(dn + br[q]) * LL + l0 + bc];
        }

        if (is64) {
#pragma unroll
            for (int kk = 0; kk < 32; kk += 8) {
                uint32_t a[2][4];
#pragma unroll
                for (int mf = 0; mf < 2; mf++) {
                    const int mo = wm * 32 + mf * 16 + g;
                    a[mf][0] = As[kk + tg    ][mo];
                    a[mf][1] = As[kk + tg    ][mo + 8];
                    a[mf][2] = As[kk + tg + 4][mo];
                    a[mf][3] = As[kk + tg + 4][mo + 8];
                }
#pragma unroll
                for (int nf = 0; nf < 8; nf++) {
                    const int nc = wn * 64 + nf * 8 + g;
                    const uint32_t b0 = Bs[kk + tg    ][nc];
                    const uint32_t b1 = Bs[kk + tg + 4][nc];
                    mma_tf32(acc[0][nf], a[0][0], a[0][1], a[0][2], a[0][3], b0, b1);
                    mma_tf32(acc[1][nf], a[1][0], a[1][1], a[1][2], a[1][3], b0, b1);
                }
            }
        } else {
#pragma unroll
            for (int kk = 0; kk < 32; kk += 8) {
                const int mo = wm * 16 + g;
                const uint32_t a0 = As[kk + tg    ][mo];
                const uint32_t a1 = As[kk + tg    ][mo + 8];
                const uint32_t a2 = As[kk + tg + 4][mo];
                const uint32_t a3 = As[kk + tg + 4][mo + 8];
#pragma unroll
                for (int nf = 0; nf < 8; nf++) {
                    const int nc = wn * 64 + nf * 8 + g;
                    const uint32_t b0 = Bs[kk + tg    ][nc];
                    const uint32_t b1 = Bs[kk + tg + 4][nc];
                    mma_tf32(acc[0][nf], a0, a1, a2, a3, b0, b1);
                }
            }
        }
        __syncthreads();
    }

    float* dtO = (kh ? g_dt1 : g_dt0);
    float* bcO = (kh ? g_bc1 : g_bc0) + (size_t)b * LL * 32;
    if (is64) {
#pragma unroll
        for (int mf = 0; mf < 2; mf++) {
            const int row0 = m0 + wm * 32 + mf * 16 + g;
            const int row1 = row0 + 8;
#pragma unroll
            for (int nf = 0; nf < 8; nf++) {
                const int col = l0 + wn * 64 + nf * 8 + 2 * tg;
                float2 v0 = {acc[mf][nf][0], acc[mf][nf][1]};
                float2 v1 = {acc[mf][nf][2], acc[mf][nf][3]};
                *(float2*)&dtO[((size_t)b * RR + row0) * LL + col] = v0;
                *(float2*)&dtO[((size_t)b * RR + row1) * LL + col] = v1;
            }
        }
    } else {
        const int row0 = m0 + wm * 16 + g;      // 128..159
        const int row1 = row0 + 8;
        const int i0 = qidx(row0 - RR);
        const int i1 = qidx(row1 - RR);
#pragma unroll
        for (int nf = 0; nf < 8; nf++) {
            const int col = l0 + wn * 64 + nf * 8 + 2 * tg;
            bcO[(size_t)(col    ) * 32 + i0] = acc[0][nf][0];
            bcO[(size_t)(col + 1) * 32 + i0] = acc[0][nf][1];
            bcO[(size_t)(col    ) * 32 + i1] = acc[0][nf][2];
            bcO[(size_t)(col + 1) * 32 + i1] = acc[0][nf][3];
        }
    }
}

// ---------------------------------------------------------------------------
// GEMM2 (tf32 TC) + softplus: delta[b,d,l] = softplus(sum_r W2[d,r]*dt[b,r,l] + bias[d])
// Block tile 128(M=d) x 128(N=l), K(r)=128 in chunks of 32. 8 warps (4m x 2n).
// dt = g_dt0 + g_dt1 (split-k partials summed at staging).
// ---------------------------------------------------------------------------
__global__ __launch_bounds__(256) void gemm2_tc(const float* __restrict__ w2,
                                                const float* __restrict__ bias)
{
    const int b  = blockIdx.z;
    const int d0 = blockIdx.y * 128;
    const int l0 = blockIdx.x * 128;

    __shared__ uint32_t As[32][132];    // [k(r)][d] tf32
    __shared__ uint32_t Bs[32][132];    // [k(r)][l] tf32

    const int tid  = threadIdx.x;
    const int warp = tid >> 5;
    const int lane = tid & 31;
    const int wmB  = (warp >> 1) * 32;
    const int wnB  = (warp & 1) * 64;
    const int g    = lane >> 2;
    const int tg   = lane & 3;

    const int Ai[4] = { tid >> 3, (tid+256)>>3, (tid+512)>>3, (tid+768)>>3 };  // d 0..127
    const int Aj    = (tid & 7) * 4;                                           // r 0..28
    const int Br[4] = { tid >> 5, (tid+256)>>5, (tid+512)>>5, (tid+768)>>5 };  // r 0..31
    const int Bc    = (tid & 31) * 4;                                          // l 0..124

    float4 sA[4], sB[4], sBb[4];
#pragma unroll
    for (int q = 0; q < 4; q++) {
        const size_t off = ((size_t)b * RR + Br[q]) * LL + l0 + Bc;
        sA[q]  = *(const float4*)&w2[(size_t)(d0 + Ai[q]) * RR + Aj];
        sB[q]  = *(const float4*)&g_dt0[off];
        sBb[q] = *(const float4*)&g_dt1[off];
    }

    float acc[2][8][4];
#pragma unroll
    for (int mf = 0; mf < 2; mf++)
#pragma unroll
        for (int nf = 0; nf < 8; nf++)
#pragma unroll
            for (int r = 0; r < 4; r++) acc[mf][nf][r] = 0.f;

    for (int r0 = 0; r0 < RR; r0 += 32) {
#pragma unroll
        for (int q = 0; q < 4; q++) {
            As[Aj + 0][Ai[q]] = f2tf(sA[q].x);
            As[Aj + 1][Ai[q]] = f2tf(sA[q].y);
            As[Aj + 2][Ai[q]] = f2tf(sA[q].z);
            As[Aj + 3][Ai[q]] = f2tf(sA[q].w);
            uint4 tv = {f2tf(sB[q].x + sBb[q].x), f2tf(sB[q].y + sBb[q].y),
                        f2tf(sB[q].z + sBb[q].z), f2tf(sB[q].w + sBb[q].w)};
            *(uint4*)&Bs[Br[q]][Bc] = tv;
        }
        __syncthreads();

        const int rn = r0 + 32;
        if (rn < RR) {
#pragma unroll
            for (int q = 0; q < 4; q++) {
                const size_t off = ((size_t)b * RR + rn + Br[q]) * LL + l0 + Bc;
                sA[q]  = *(const float4*)&w2[(size_t)(d0 + Ai[q]) * RR + rn + Aj];
                sB[q]  = *(const float4*)&g_dt0[off];
                sBb[q] = *(const float4*)&g_dt1[off];
            }
        }

#pragma unroll
        for (int kk = 0; kk < 32; kk += 8) {
            uint32_t a[2][4];
#pragma unroll
            for (int mf = 0; mf < 2; mf++) {
                a[mf][0] = As[kk + tg    ][wmB + mf * 16 + g];
                a[mf][1] = As[kk + tg    ][wmB + mf * 16 + g + 8];
                a[mf][2] = As[kk + tg + 4][wmB + mf * 16 + g];
                a[mf][3] = As[kk + tg + 4][wmB + mf * 16 + g + 8];
            }
#pragma unroll
            for (int nf = 0; nf < 8; nf++) {
                const int nc = wnB + nf * 8 + g;
                const uint32_t b0 = Bs[kk + tg    ][nc];
                const uint32_t b1 = Bs[kk + tg + 4][nc];
#pragma unroll
                for (int mf = 0; mf < 2; mf++)
                    mma_tf32(acc[mf][nf], a[mf][0], a[mf][1], a[mf][2], a[mf][3], b0, b1);
            }
        }
        __syncthreads();
    }

#pragma unroll
    for (int mf = 0; mf < 2; mf++) {
        const int row0 = d0 + wmB + mf * 16 + g;
        const int row1 = row0 + 8;
        const float bi0 = bias[row0];
        const float bi1 = bias[row1];
#pragma unroll
        for (int nf = 0; nf < 8; nf++) {
            const int col = l0 + wnB + nf * 8 + 2 * tg;
            float2 v0 = {softplus_fast(acc[mf][nf][0] + bi0),
                         softplus_fast(acc[mf][nf][1] + bi0)};
            float2 v1 = {softplus_fast(acc[mf][nf][2] + bi1),
                         softplus_fast(acc[mf][nf][3] + bi1)};
            *(float2*)&g_delta[((size_t)b * DIN + row0) * LL + col] = v0;
            *(float2*)&g_delta[((size_t)b * DIN + row1) * LL + col] = v1;
        }
    }
}

// ---------------------------------------------------------------------------
// Scan v4: 128 threads = 16 groups of 8 lanes; lane n owns states n and n+8.
// B/C quads [B_n, C_n, B_{n+8}, C_{n+8}] -> one LDS.128 per step per lane.
// Chunks of 32 timesteps staged in smem; bc = sum of split-k partials.
// ---------------------------------------------------------------------------
#define CH 32
__global__ __launch_bounds__(128) void scan_kernel(const float* __restrict__ x,
                                                   const float* __restrict__ A_log,
                                                   const float* __restrict__ Dvec,
                                                   float* __restrict__ y)
{
    __shared__ float del_s[16][CH];
    __shared__ float x_s[16][CH];
    __shared__ float bc_s[CH * 32];

    const int tid = threadIdx.x;
    const int lg  = tid >> 3;            // local group 0..15
    const int n   = tid & 7;             // lane within group
    const int gb  = blockIdx.x * 16;     // (b,d)-group base
    const int b   = gb >> 12;
    const int dbase = gb & 4095;
    const int d   = dbase + lg;

    const size_t base = ((size_t)b * DIN + d) * LL;
    const float  a0   = -__expf(A_log[d * NN + n]);
    const float  a1   = -__expf(A_log[d * NN + n + 8]);
    const float  dD   = (n == 0) ? Dvec[d] : 0.f;
    const int jm = ((n & 1) << 1) | ((n >> 1) & 1);

    const float* bc0 = g_bc0 + (size_t)b * LL * 32;
    const float* bc1 = g_bc1 + (size_t)b * LL * 32;

    const int srow = tid >> 3;                 // 0..15 (delta/x row)
    const int scol = (tid & 7) * 4;            // 0..28 (chunk offset)
    const size_t rowoff = ((size_t)b * DIN + dbase + srow) * LL;
    const int bcol[2] = { tid >> 3, (tid + 128) >> 3 };
    const int boff[2] = { (tid & 7) * 4, (tid & 7) * 4 };

    float4 rbc[2], rdel, rx;
#pragma unroll
    for (int q = 0; q < 2; q++) {
        const size_t o = (size_t)bcol[q] * 32 + boff[q];
        float4 v0 = *(const float4*)&bc0[o];
        float4 v1 = *(const float4*)&bc1[o];
        rbc[q] = make_float4(v0.x + v1.x, v0.y + v1.y, v0.z + v1.z, v0.w + v1.w);
    }
    rdel = *(const float4*)&g_delta[rowoff + scol];
    rx   = *(const float4*)&x[rowoff + scol];

    float h0 = 0.f, h1 = 0.f;
    for (int l0 = 0; l0 < LL; l0 += CH) {
#pragma unroll
        for (int q = 0; q < 2; q++)
            *(float4*)&bc_s[bcol[q] * 32 + boff[q]] = rbc[q];
        *(float4*)&del_s[srow][scol] = rdel;
        *(float4*)&x_s[srow][scol]   = rx;
        __syncthreads();

        const int ln = l0 + CH;
        if (ln < LL) {
#pragma unroll
            for (int q = 0; q < 2; q++) {
                const size_t o = (size_t)(ln + bcol[q]) * 32 + boff[q];
                float4 v0 = *(const float4*)&bc0[o];
                float4 v1 = *(const float4*)&bc1[o];
                rbc[q] = make_float4(v0.x + v1.x, v0.y + v1.y, v0.z + v1.z, v0.w + v1.w);
            }
            rdel = *(const float4*)&g_delta[rowoff + ln + scol];
            rx   = *(const float4*)&x[rowoff + ln + scol];
        }

#pragma unroll
        for (int jj = 0; jj < CH; jj += 4) {
            const float4 tz = *(const float4*)&del_s[lg][jj];
            const float4 uu = *(const float4*)&x_s[lg][jj];
            const float tj[4] = {tz.x, tz.y, tz.z, tz.w};
            const float uj[4] = {uu.x, uu.y, uu.z, uu.w};
            float p[4];
#pragma unroll
            for (int j = 0; j < 4; j++) {
                const float t = tj[j];
                const float u = uj[j];
                const float4 q = *(const float4*)&bc_s[(jj + j) * 32 + n * 4];
                const float e0 = __expf(t * a0);
                const float e1 = __expf(t * a1);
                const float tu = t * u;
                h0 = fmaf(h0, e0, tu * q.x);
                h1 = fmaf(h1, e1, tu * q.z);
                p[j] = fmaf(h0, q.y, fmaf(h1, q.w, u * dD));
            }
            const bool o1 = (n & 1);
            float s0 = o1 ? p[0] : p[2];
            float s1 = o1 ? p[1] : p[3];
            float r0 = __shfl_xor_sync(0xffffffffu, s0, 1);
            float r1 = __shfl_xor_sync(0xffffffffu, s1, 1);
            float u0 = (o1 ? p[2] : p[0]) + r0;
            float u1 = (o1 ? p[3] : p[1]) + r1;
            const bool o2 = (n & 2);
            float s2 = o2 ? u0 : u1;
            float r2 = __shfl_xor_sync(0xffffffffu, s2, 2);
            float v  = (o2 ? u1 : u0) + r2;
            v += __shfl_xor_sync(0xffffffffu, v, 4);
            if (n < 4) y[base + l0 + jj + jm] = v;
        }
        __syncthreads();
    }
}

// ---------------------------------------------------------------------------
extern "C" void kernel_launch(void* const* d_in, const int* in_sizes, int n_in,
                              void* d_out, int out_size)
{
    const float* x     = (const float*)d_in[0];  // (B, D, L)
    const float* A_log = (const float*)d_in[1];  // (D, N)
    const float* Dvec  = (const float*)d_in[2];  // (D,)
    const float* xpw   = (const float*)d_in[3];  // (160, D)
    const float* dtw   = (const float*)d_in[4];  // (D, R)
    const float* dtb   = (const float*)d_in[5];  // (D,)
    float* y = (float*)d_out;

    {
        dim3 grid(LL / 128, 3, B_ * 2);       // 32 x 3 x 4 = 384 (split-k, 64-row tiles)
        gemm1_tc<<<grid, 128>>>(x, xpw);
    }
    {
        dim3 grid(LL / 128, DIN / 128, B_);   // 32 x 32 x 2 = 2048
        gemm2_tc<<<grid, 256>>>(dtw, dtb);
    }
    {
        const int blocks = (B_ * DIN) / 16;   // 512 blocks of 16 groups
        scan_kernel<<<blocks, 128>>>(x, A_log, Dvec, y);
    }
}